// round 11
// baseline (speedup 1.0000x reference)
#include <cuda_runtime.h>
#include <cuda_fp16.h>
#include <math.h>
#include <stdint.h>

#define BB 16
#define CC 384
#define HH 64
#define WW 64
#define NHEADS 8
#define HD 48
#define NGROUPS 4
#define CPG 96
#define NTOK (BB*HH*WW)     // 65536 tokens
#define EPSV 1e-5

// ---------------- scratch (static device globals; no allocations) ----------------
__device__ double g_part[BB*NGROUPS*16];
__device__ double g_part2[BB*NGROUPS*16];
__device__ __half g_y[(size_t)NTOK*CC];       // normalized windowed tokens (fp16, GEMM A)
__device__ __half g_qkv[(size_t)NTOK*3*CC];   // qkv projections (fp16)
__device__ __half g_o[(size_t)NTOK*CC];       // fused attn+proj output (fp16)
__device__ __half g_wqkv[(size_t)3*CC*CC];    // fp16 weights
__device__ __half g_wproj[(size_t)CC*CC];

// ==================== PTX helpers ====================
__device__ __forceinline__ uint32_t smem_u32(const void* p) {
    uint32_t a;
    asm("{ .reg .u64 t; cvta.to.shared.u64 t, %1; cvt.u32.u64 %0, t; }" : "=r"(a) : "l"(p));
    return a;
}
__device__ __forceinline__ void cp_async16(uint32_t dst, const void* src) {
    asm volatile("cp.async.cg.shared.global [%0], [%1], 16;" :: "r"(dst), "l"(src) : "memory");
}
#define CP_COMMIT() asm volatile("cp.async.commit_group;" ::: "memory")

#define LDSM4(r0, r1, r2, r3, a)                                               \
    asm volatile("ldmatrix.sync.aligned.m8n8.x4.shared.b16 {%0,%1,%2,%3}, [%4];"\
                 : "=r"(r0), "=r"(r1), "=r"(r2), "=r"(r3) : "r"(a))

#define LDSM4T(r0, r1, r2, r3, a)                                              \
    asm volatile("ldmatrix.sync.aligned.m8n8.x4.trans.shared.b16 {%0,%1,%2,%3}, [%4];"\
                 : "=r"(r0), "=r"(r1), "=r"(r2), "=r"(r3) : "r"(a))

#define MMA16(d, a, b0, b1)                                                    \
    asm volatile("mma.sync.aligned.m16n8k16.row.col.f32.f16.f16.f32 "          \
                 "{%0,%1,%2,%3}, {%4,%5,%6,%7}, {%8,%9}, {%0,%1,%2,%3};"       \
                 : "+f"((d)[0]), "+f"((d)[1]), "+f"((d)[2]), "+f"((d)[3])      \
                 : "r"((a)[0]), "r"((a)[1]), "r"((a)[2]), "r"((a)[3]),         \
                   "r"(b0), "r"(b1))

// ---------------- 0) weight conversion fp32 -> fp16 (both weights, one launch) ----------------
#define N4Q (3*CC*CC/4)
#define N4P (CC*CC/4)
__global__ void k_cvtw(const float* __restrict__ wq, const float* __restrict__ wp) {
    int i = blockIdx.x * 256 + threadIdx.x;
    if (i < N4Q) {
        float4 v = ((const float4*)wq)[i];
        ((__half2*)g_wqkv)[2*i]   = __floats2half2_rn(v.x, v.y);
        ((__half2*)g_wqkv)[2*i+1] = __floats2half2_rn(v.z, v.w);
    } else if (i < N4Q + N4P) {
        int j = i - N4Q;
        float4 v = ((const float4*)wp)[j];
        ((__half2*)g_wproj)[2*j]   = __floats2half2_rn(v.x, v.y);
        ((__half2*)g_wproj)[2*j+1] = __floats2half2_rn(v.z, v.w);
    }
}

// ---------------- 1) GroupNorm partial sums: 1024 blocks ----------------
__global__ void k_gnstats1(const float* __restrict__ x) {
    const int bg = blockIdx.x >> 4;
    const int sl = blockIdx.x & 15;
    const float4* p = (const float4*)(x + (size_t)bg * CPG * HH * WW) + sl * 6144;
    float s = 0.f, s2 = 0.f;
#pragma unroll
    for (int j = 0; j < 24; j++) {
        float4 v = p[j * 256 + threadIdx.x];
        s  += v.x + v.y + v.z + v.w;
        s2 += v.x*v.x + v.y*v.y + v.z*v.z + v.w*v.w;
    }
    __shared__ double ss[256], ss2[256];
    ss[threadIdx.x] = (double)s; ss2[threadIdx.x] = (double)s2;
    __syncthreads();
    for (int st = 128; st > 0; st >>= 1) {
        if (threadIdx.x < st) {
            ss[threadIdx.x]  += ss[threadIdx.x + st];
            ss2[threadIdx.x] += ss2[threadIdx.x + st];
        }
        __syncthreads();
    }
    if (threadIdx.x == 0) {
        g_part[blockIdx.x]  = ss[0];
        g_part2[blockIdx.x] = ss2[0];
    }
}

// ------- 2) finalize stats + normalize + affine + window-pack -> y[token, C] fp16 -------
__global__ void k_pack(const float* __restrict__ x,
                       const float* __restrict__ gw,
                       const float* __restrict__ gb) {
    __shared__ float sm[128 * 65];
    __shared__ float s_mean[2], s_rstd[2];
    const int c0 = blockIdx.x * 128;
    const int h  = blockIdx.y;
    const int b  = blockIdx.z;
    const int tid = threadIdx.x;

    const int g_lo = c0 / CPG;
    const int g_hi = (c0 + 127) / CPG;
    if (tid < 64) {
        const int slot = tid >> 5;
        const int g    = slot ? g_hi : g_lo;
        const int lane = tid & 31;
        const int bg   = b * 4 + g;
        double s  = (lane < 16) ? g_part[bg * 16 + lane]  : 0.0;
        double s2 = (lane < 16) ? g_part2[bg * 16 + lane] : 0.0;
#pragma unroll
        for (int o = 8; o > 0; o >>= 1) {
            s  += __shfl_down_sync(0xffffffffu, s, o);
            s2 += __shfl_down_sync(0xffffffffu, s2, o);
        }
        if (lane == 0) {
            const double cnt = (double)(CPG * HH * WW);
            double m   = s / cnt;
            double var = s2 / cnt - m * m;
            s_mean[slot] = (float)m;
            s_rstd[slot] = (float)rsqrt(var + EPSV);
        }
    }
    __syncthreads();

#pragma unroll
    for (int r = 0; r < 8; r++) {
        int i  = r * 256 + tid;
        int w4 = i & 15;
        int cl = i >> 4;
        int c  = c0 + cl;
        int gs = (c / CPG) != g_lo;
        float mu = s_mean[gs], rs = s_rstd[gs];
        float sc = rs * gw[c];
        float sh = gb[c] - mu * sc;
        float4 v = *(const float4*)(x + (((size_t)b * CC + c) * HH + h) * WW + 4 * w4);
        sm[cl * 65 + 4*w4]     = v.x * sc + sh;
        sm[cl * 65 + 4*w4 + 1] = v.y * sc + sh;
        sm[cl * 65 + 4*w4 + 2] = v.z * sc + sh;
        sm[cl * 65 + 4*w4 + 3] = v.w * sc + sh;
    }
    __syncthreads();

    const int hb = h >> 3, hs = h & 7;
#pragma unroll
    for (int it = 0; it < 4; it++) {
        int i  = it * 256 + tid;
        int c8 = i & 15;
        int w  = i >> 4;
        int n  = (b * 8 + hb) * 8 + (w >> 3);
        int s  = hs * 8 + (w & 7);
        float v[8];
#pragma unroll
        for (int j = 0; j < 8; j++) {
            int jj = (j + c8) & 7;
            v[jj] = sm[(c8 * 8 + jj) * 65 + w];
        }
        __half2 h0 = __floats2half2_rn(v[0], v[1]);
        __half2 h1 = __floats2half2_rn(v[2], v[3]);
        __half2 h2 = __floats2half2_rn(v[4], v[5]);
        __half2 h3 = __floats2half2_rn(v[6], v[7]);
        uint4 pk = make_uint4(*(uint32_t*)&h0, *(uint32_t*)&h1,
                              *(uint32_t*)&h2, *(uint32_t*)&h3);
        *(uint4*)(g_y + ((size_t)n * 64 + s) * CC + c0 + c8 * 8) = pk;
    }
}

// ============ 3) fp16 GEMM (qkv): M-tile 64, 256 threads, 8 warps (2x4), 32x32 warp tiles ============
// Finer grid (1024 CTAs) -> 6.92 waves, kills wave-quantization tail.
// A tile 64x384 (48KB) resident; B in K=128-half chunks (32KB), 3 bufs, 1 sync/chunk.
#define GEMM_SMEM (49152 + 3*32768)  // 147456
#define A_PITCH 768
#define MTILE 64

__device__ __forceinline__ void load_B_chunk(const __half* __restrict__ Bw,
                                             uint32_t dst, int tid) {
#pragma unroll
    for (int j = 0; j < 8; j++) {
        int idx = j * 256 + tid;
        int n = idx >> 4, u = idx & 15;
        int phys = (u & ~7) | ((u & 7) ^ (n & 7));
        cp_async16(dst + n * 256 + (phys << 4), Bw + (size_t)n * CC + u * 8);
    }
    CP_COMMIT();
}

__global__ void __launch_bounds__(256)
k_hgemm(int N, int ntiles) {
    extern __shared__ char smem[];
    const uint32_t sbA = smem_u32(smem);
    const uint32_t sbB = sbA + 49152;
    const int tid  = threadIdx.x;
    const int lane = tid & 31;
    const int wrp  = tid >> 5;          // 0..7
    const int wm   = (wrp & 1) * 32;    // 2 M warp-groups
    const int wn   = (wrp >> 1) * 32;   // 4 N warp-groups

    const __half* Bw = g_wqkv;
    const __half* Ab = g_y + (size_t)blockIdx.x * MTILE * CC;

    // A tile: 64 rows x 48 units = 3072 units, 256 threads -> 12 iters
#pragma unroll
    for (int j = 0; j < 12; j++) {
        int idx = j * 256 + tid;
        int m = idx / 48, u = idx - m * 48;
        int phys = (u & ~7) | ((u & 7) ^ (m & 7));
        cp_async16(sbA + m * A_PITCH + (phys << 4), Ab + (size_t)m * CC + u * 8);
    }
    CP_COMMIT();

    const int nc = ntiles * 3;
    load_B_chunk(Bw, sbB, tid);
    load_B_chunk(Bw + 128, sbB + 32768, tid);

    const int rA  = lane & 15;
    const int uHi = lane >> 4;
    const int r   = lane >> 2;
    const int cq  = lane & 3;

    float acc[2][4][4];
#pragma unroll
    for (int mi = 0; mi < 2; mi++)
#pragma unroll
        for (int ni = 0; ni < 4; ni++)
#pragma unroll
            for (int e = 0; e < 4; e++) acc[mi][ni][e] = 0.f;

    for (int nt = 0; nt < ntiles; nt++) {
#pragma unroll
        for (int kc = 0; kc < 3; kc++) {
            const int i = nt * 3 + kc;
            if (i < nc - 1) asm volatile("cp.async.wait_group 1;" ::: "memory");
            else            asm volatile("cp.async.wait_group 0;" ::: "memory");
            __syncthreads();

            if (i + 2 < nc) {
                const int nxt = i + 2;
                load_B_chunk(Bw + (size_t)((nxt / 3) * 128) * CC + (nxt % 3) * 128,
                             sbB + (uint32_t)((kc + 2) % 3) * 32768, tid);
            }

            const uint32_t bbase = sbB + (uint32_t)kc * 32768;
#pragma unroll
            for (int ks = 0; ks < 8; ks++) {
                const int ugA = kc * 16 + ks * 2 + uHi;
                const int ulB = ks * 2 + uHi;
                uint32_t af[2][4], bf[2][4];
#pragma unroll
                for (int mi = 0; mi < 2; mi++) {
                    int m = wm + mi * 16 + rA;
                    int phys = (ugA & ~7) | ((ugA & 7) ^ (m & 7));
                    LDSM4(af[mi][0], af[mi][1], af[mi][2], af[mi][3],
                          sbA + (uint32_t)(m * A_PITCH + (phys << 4)));
                }
#pragma unroll
                for (int g = 0; g < 2; g++) {
                    int n = wn + g * 16 + rA;
                    int phys = (ulB & ~7) | ((ulB & 7) ^ (n & 7));
                    LDSM4(bf[g][0], bf[g][1], bf[g][2], bf[g][3],
                          bbase + (uint32_t)(n * 256 + (phys << 4)));
                }
#pragma unroll
                for (int mi = 0; mi < 2; mi++)
#pragma unroll
                    for (int ni = 0; ni < 4; ni++)
                        MMA16(acc[mi][ni], af[mi], bf[ni >> 1][ni & 1], bf[ni >> 1][2 + (ni & 1)]);
            }
        }

#pragma unroll
        for (int mi = 0; mi < 2; mi++) {
            const int row0 = blockIdx.x * MTILE + wm + mi * 16 + r;
#pragma unroll
            for (int ni = 0; ni < 4; ni++) {
                const int col = nt * 128 + wn + ni * 8 + cq * 2;
                *(__half2*)(g_qkv + (size_t)row0 * N + col) =
                    __floats2half2_rn(acc[mi][ni][0], acc[mi][ni][1]);
                *(__half2*)(g_qkv + (size_t)(row0 + 8) * N + col) =
                    __floats2half2_rn(acc[mi][ni][2], acc[mi][ni][3]);
                acc[mi][ni][0] = acc[mi][ni][1] = acc[mi][ni][2] = acc[mi][ni][3] = 0.f;
            }
        }
    }
}

// ============ 4) fused attention + proj: 1 block = 1 window, 16 warps ============
#define ATTN_SMEM (147456 + 49152)   // 196608
#define H_PITCH 768

__global__ void __launch_bounds__(512, 1) k_attn_proj(const float* __restrict__ bias) {
    extern __shared__ char smem[];
    const uint32_t sb  = smem_u32(smem);
    const uint32_t sbH = sb + 147456;
    const int tid  = threadIdx.x;
    const int lane = tid & 31;
    const int wrp  = tid >> 5;
    const int head = wrp >> 1;
    const int hlf  = wrp & 1;
    const int win  = blockIdx.x;

    const __half* src = g_qkv + (size_t)win * 64 * 1152;
#pragma unroll
    for (int j = 0; j < 18; j++) {
        int idx = j * 512 + tid;
        int t = idx / 144, c = idx % 144;
        cp_async16(sb + t * 2304 + ((c ^ (t & 7)) << 4), src + (size_t)t * 1152 + c * 8);
    }
    CP_COMMIT();
    asm volatile("cp.async.wait_group 0;" ::: "memory");
    __syncthreads();

    const int rA = lane & 15;
    const int hi = lane >> 4;
    const int qcb = head * 6;
    const int kcb = 48 + head * 6;
    const int vcb = 96 + head * 6;

    float S[2][8][4];
#pragma unroll
    for (int mi = 0; mi < 2; mi++)
#pragma unroll
        for (int ni = 0; ni < 8; ni++)
#pragma unroll
            for (int e = 0; e < 4; e++) S[mi][ni][e] = 0.f;

#pragma unroll
    for (int kt = 0; kt < 3; kt++) {
        uint32_t aq[2][4];
#pragma unroll
        for (int mi = 0; mi < 2; mi++) {
            int m = hlf * 32 + mi * 16 + rA;
            uint32_t a = sb + m * 2304 + (((qcb + kt * 2 + hi) ^ (m & 7)) << 4);
            LDSM4(aq[mi][0], aq[mi][1], aq[mi][2], aq[mi][3], a);
        }
#pragma unroll
        for (int g = 0; g < 4; g++) {
            int n = g * 16 + rA;
            uint32_t a = sb + n * 2304 + (((kcb + kt * 2 + hi) ^ (n & 7)) << 4);
            uint32_t b0, b1, b2, b3;
            LDSM4(b0, b1, b2, b3, a);
#pragma unroll
            for (int mi = 0; mi < 2; mi++) {
                MMA16(S[mi][2*g],     aq[mi], b0, b2);
                MMA16(S[mi][2*g + 1], aq[mi], b1, b3);
            }
        }
    }

    const float cs = 0.14433756729740643f * 1.4426950408889634f;
    float mx[2][2];
#pragma unroll
    for (int mi = 0; mi < 2; mi++) { mx[mi][0] = -1e30f; mx[mi][1] = -1e30f; }
#pragma unroll
    for (int mi = 0; mi < 2; mi++)
#pragma unroll
        for (int ni = 0; ni < 8; ni++) {
            mx[mi][0] = fmaxf(mx[mi][0], fmaxf(S[mi][ni][0], S[mi][ni][1]));
            mx[mi][1] = fmaxf(mx[mi][1], fmaxf(S[mi][ni][2], S[mi][ni][3]));
        }
#pragma unroll
    for (int mi = 0; mi < 2; mi++)
#pragma unroll
        for (int e = 0; e < 2; e++) {
            mx[mi][e] = fmaxf(mx[mi][e], __shfl_xor_sync(0xffffffffu, mx[mi][e], 1));
            mx[mi][e] = fmaxf(mx[mi][e], __shfl_xor_sync(0xffffffffu, mx[mi][e], 2));
        }

    uint32_t P[2][4][4];
    float sum[2][2] = {{0.f, 0.f}, {0.f, 0.f}};
#pragma unroll
    for (int mi = 0; mi < 2; mi++)
#pragma unroll
        for (int kt = 0; kt < 4; kt++)
#pragma unroll
            for (int q = 0; q < 2; q++) {
                const int ni = 2 * kt + q;
                float e0 = exp2f((S[mi][ni][0] - mx[mi][0]) * cs);
                float e1 = exp2f((S[mi][ni][1] - mx[mi][0]) * cs);
                float e2 = exp2f((S[mi][ni][2] - mx[mi][1]) * cs);
                float e3 = exp2f((S[mi][ni][3] - mx[mi][1]) * cs);
                sum[mi][0] += e0 + e1;
                sum[mi][1] += e2 + e3;
                __half2 h0 = __floats2half2_rn(e0, e1);
                __half2 h1 = __floats2half2_rn(e2, e3);
                P[mi][kt][2*q]     = *(uint32_t*)&h0;
                P[mi][kt][2*q + 1] = *(uint32_t*)&h1;
            }
#pragma unroll
    for (int mi = 0; mi < 2; mi++)
#pragma unroll
        for (int e = 0; e < 2; e++) {
            sum[mi][e] += __shfl_xor_sync(0xffffffffu, sum[mi][e], 1);
            sum[mi][e] += __shfl_xor_sync(0xffffffffu, sum[mi][e], 2);
        }

    float O[2][6][4];
#pragma unroll
    for (int mi = 0; mi < 2; mi++)
#pragma unroll
        for (int ni = 0; ni < 6; ni++)
#pragma unroll
            for (int e = 0; e < 4; e++) O[mi][ni][e] = 0.f;

#pragma unroll
    for (int kt = 0; kt < 4; kt++) {
#pragma unroll
        for (int p = 0; p < 3; p++) {
            int t = kt * 16 + rA;
            uint32_t a = sb + t * 2304 + (((vcb + 2*p + hi) ^ (t & 7)) << 4);
            uint32_t v0, v1, v2, v3;
            LDSM4T(v0, v1, v2, v3, a);
#pragma unroll
            for (int mi = 0; mi < 2; mi++) {
                MMA16(O[mi][2*p],     P[mi][kt], v0, v1);
                MMA16(O[mi][2*p + 1], P[mi][kt], v2, v3);
            }
        }
    }

    const int r  = lane >> 2;
    const int cq = lane & 3;
#pragma unroll
    for (int mi = 0; mi < 2; mi++) {
        const float i0 = 1.f / sum[mi][0];
        const float i1 = 1.f / sum[mi][1];
#pragma unroll
        for (int ni = 0; ni < 6; ni++) {
            const int u = head * 6 + ni;
            const int m0 = hlf * 32 + mi * 16 + r;
            const int m1 = m0 + 8;
            __half2 h0 = __floats2half2_rn(O[mi][ni][0] * i0, O[mi][ni][1] * i0);
            __half2 h1 = __floats2half2_rn(O[mi][ni][2] * i1, O[mi][ni][3] * i1);
            int ph0 = (u & ~7) | ((u & 7) ^ (m0 & 7));
            int ph1 = (u & ~7) | ((u & 7) ^ (m1 & 7));
            *(uint32_t*)(smem + 147456 + m0 * H_PITCH + (ph0 << 4) + cq * 4) = *(uint32_t*)&h0;
            *(uint32_t*)(smem + 147456 + m1 * H_PITCH + (ph1 << 4) + cq * 4) = *(uint32_t*)&h1;
        }
    }
    __syncthreads();

    const int wm2 = (wrp & 1) * 32;
    const int wn2 = (wrp >> 1) * 48;
    const __half* Wp = g_wproj;

#define LOAD_W(cI, bI)                                                          \
    {                                                                           \
        const uint32_t dstw = sb + (uint32_t)(bI) * 49152;                      \
        _Pragma("unroll")                                                       \
        for (int j = 0; j < 6; j++) {                                           \
            int idx = j * 512 + tid;                                            \
            int n = idx >> 3, u = idx & 7;                                      \
            cp_async16(dstw + n * 128 + ((u ^ (n & 7)) << 4),                   \
                       Wp + (size_t)n * CC + (cI) * 64 + u * 8);                \
        }                                                                       \
        CP_COMMIT();                                                            \
    }

    LOAD_W(0, 0);
    LOAD_W(1, 1);

    float acc2[2][6][4];
#pragma unroll
    for (int mi = 0; mi < 2; mi++)
#pragma unroll
        for (int ni = 0; ni < 6; ni++)
#pragma unroll
            for (int e = 0; e < 4; e++) acc2[mi][ni][e] = 0.f;

    for (int c = 0; c < 6; c++) {
        if (c < 5) asm volatile("cp.async.wait_group 1;" ::: "memory");
        else       asm volatile("cp.async.wait_group 0;" ::: "memory");
        __syncthreads();

        if (c + 2 < 6) LOAD_W(c + 2, (c + 2) % 3);

        const uint32_t wbase = sb + (uint32_t)(c % 3) * 49152;
#pragma unroll
        for (int ks = 0; ks < 4; ks++) {
            const int ugA = c * 8 + ks * 2 + hi;
            const int ulB = ks * 2 + hi;
            uint32_t af[2][4], bf[3][4];
#pragma unroll
            for (int mi = 0; mi < 2; mi++) {
                int m = wm2 + mi * 16 + rA;
                int phys = (ugA & ~7) | ((ugA & 7) ^ (m & 7));
                LDSM4(af[mi][0], af[mi][1], af[mi][2], af[mi][3],
                      sbH + (uint32_t)(m * H_PITCH + (phys << 4)));
            }
#pragma unroll
            for (int g = 0; g < 3; g++) {
                int n = wn2 + g * 16 + rA;
                int phys = ulB ^ (n & 7);
                LDSM4(bf[g][0], bf[g][1], bf[g][2], bf[g][3],
                      wbase + (uint32_t)(n * 128 + (phys << 4)));
            }
#pragma unroll
            for (int mi = 0; mi < 2; mi++)
#pragma unroll
                for (int g = 0; g < 3; g++) {
                    MMA16(acc2[mi][2*g],     af[mi], bf[g][0], bf[g][2]);
                    MMA16(acc2[mi][2*g + 1], af[mi], bf[g][1], bf[g][3]);
                }
        }
    }

    __half* dst = g_o + (size_t)win * 64 * CC;
#pragma unroll
    for (int mi = 0; mi < 2; mi++) {
        const int m0 = wm2 + mi * 16 + r;
#pragma unroll
        for (int ni = 0; ni < 6; ni++) {
            const int col = wn2 + ni * 8 + 2 * cq;
            float b0 = bias[col], b1 = bias[col + 1];
            *(__half2*)(dst + (size_t)m0 * CC + col) =
                __floats2half2_rn(acc2[mi][ni][0] + b0, acc2[mi][ni][1] + b1);
            *(__half2*)(dst + (size_t)(m0 + 8) * CC + col) =
                __floats2half2_rn(acc2[mi][ni][2] + b0, acc2[mi][ni][3] + b1);
        }
    }
}

// --------- 6) un-window + residual:  g_o[token,C] fp16 -> out(B,C,H,W) += x ---------
__global__ void k_unpack(const float* __restrict__ x, float* __restrict__ out) {
    __shared__ float sm[128 * 65];
    const int c0 = blockIdx.x * 128;
    const int h  = blockIdx.y;
    const int b  = blockIdx.z;
    const int tid = threadIdx.x;
    const int hb = h >> 3, hs = h & 7;
#pragma unroll
    for (int it = 0; it < 4; it++) {
        int i  = it * 256 + tid;
        int c8 = i & 15;
        int w  = i >> 4;
        int n  = (b * 8 + hb) * 8 + (w >> 3);
        int s  = hs * 8 + (w & 7);
        uint4 pk = *(const uint4*)(g_o + ((size_t)n * 64 + s) * CC + c0 + c8 * 8);
        const __half2* hp = (const __half2*)&pk;
#pragma unroll
        for (int j = 0; j < 4; j++) {
            float2 fv = __half22float2(hp[j]);
            sm[(c8 * 8 + 2*j)     * 65 + w] = fv.x;
            sm[(c8 * 8 + 2*j + 1) * 65 + w] = fv.y;
        }
    }
    __syncthreads();
#pragma unroll
    for (int r = 0; r < 8; r++) {
        int i  = r * 256 + tid;
        int w4 = i & 15;
        int cl = i >> 4;
        size_t gi = (((size_t)b * CC + c0 + cl) * HH + h) * WW + 4 * w4;
        float4 xv = *(const float4*)(x + gi);
        float4 ov;
        ov.x = sm[cl * 65 + 4*w4]     + xv.x;
        ov.y = sm[cl * 65 + 4*w4 + 1] + xv.y;
        ov.z = sm[cl * 65 + 4*w4 + 2] + xv.z;
        ov.w = sm[cl * 65 + 4*w4 + 3] + xv.w;
        *(float4*)(out + gi) = ov;
    }
}

// --------------------------------- launch ---------------------------------
extern "C" void kernel_launch(void* const* d_in, const int* in_sizes, int n_in,
                              void* d_out, int out_size) {
    const float* x     = (const float*)d_in[0];
    const float* gw    = (const float*)d_in[1];
    const float* gb    = (const float*)d_in[2];
    const float* wqkv  = (const float*)d_in[3];
    const float* wproj = (const float*)d_in[4];
    const float* bproj = (const float*)d_in[5];
    float* out = (float*)d_out;

    cudaFuncSetAttribute(k_hgemm,     cudaFuncAttributeMaxDynamicSharedMemorySize, GEMM_SMEM);
    cudaFuncSetAttribute(k_attn_proj, cudaFuncAttributeMaxDynamicSharedMemorySize, ATTN_SMEM);

    k_cvtw<<<(N4Q + N4P + 255)/256, 256>>>(wqkv, wproj);
    k_gnstats1<<<BB * NGROUPS * 16, 256>>>(x);
    k_pack<<<dim3(3, HH, BB), 256>>>(x, gw, gb);
    k_hgemm<<<NTOK / MTILE, 256, GEMM_SMEM>>>(3 * CC, 9);
    k_attn_proj<<<NTOK / 64, 512, ATTN_SMEM>>>(bproj);
    k_unpack<<<dim3(3, HH, BB), 256>>>(x, out);
}

// round 13
// speedup vs baseline: 1.0390x; 1.0390x over previous
#include <cuda_runtime.h>
#include <cuda_fp16.h>
#include <math.h>
#include <stdint.h>

#define BB 16
#define CC 384
#define HH 64
#define WW 64
#define NHEADS 8
#define HD 48
#define NGROUPS 4
#define CPG 96
#define NTOK (BB*HH*WW)     // 65536 tokens
#define EPSV 1e-5

// ---------------- scratch (static device globals; no allocations) ----------------
__device__ double g_part[BB*NGROUPS*16];
__device__ double g_part2[BB*NGROUPS*16];
__device__ __half g_y[(size_t)NTOK*CC];       // normalized windowed tokens (fp16, GEMM A)
__device__ __half g_qkv[(size_t)NTOK*3*CC];   // qkv projections (fp16)
__device__ __half g_o[(size_t)NTOK*CC];       // fused attn+proj output (fp16)
__device__ __half g_wqkv[(size_t)3*CC*CC];    // fp16 weights
__device__ __half g_wproj[(size_t)CC*CC];

// ==================== PTX helpers ====================
__device__ __forceinline__ uint32_t smem_u32(const void* p) {
    uint32_t a;
    asm("{ .reg .u64 t; cvta.to.shared.u64 t, %1; cvt.u32.u64 %0, t; }" : "=r"(a) : "l"(p));
    return a;
}
__device__ __forceinline__ void cp_async16(uint32_t dst, const void* src) {
    asm volatile("cp.async.cg.shared.global [%0], [%1], 16;" :: "r"(dst), "l"(src) : "memory");
}
#define CP_COMMIT() asm volatile("cp.async.commit_group;" ::: "memory")

#define LDSM4(r0, r1, r2, r3, a)                                               \
    asm volatile("ldmatrix.sync.aligned.m8n8.x4.shared.b16 {%0,%1,%2,%3}, [%4];"\
                 : "=r"(r0), "=r"(r1), "=r"(r2), "=r"(r3) : "r"(a))

#define LDSM4T(r0, r1, r2, r3, a)                                              \
    asm volatile("ldmatrix.sync.aligned.m8n8.x4.trans.shared.b16 {%0,%1,%2,%3}, [%4];"\
                 : "=r"(r0), "=r"(r1), "=r"(r2), "=r"(r3) : "r"(a))

#define MMA16(d, a, b0, b1)                                                    \
    asm volatile("mma.sync.aligned.m16n8k16.row.col.f32.f16.f16.f32 "          \
                 "{%0,%1,%2,%3}, {%4,%5,%6,%7}, {%8,%9}, {%0,%1,%2,%3};"       \
                 : "+f"((d)[0]), "+f"((d)[1]), "+f"((d)[2]), "+f"((d)[3])      \
                 : "r"((a)[0]), "r"((a)[1]), "r"((a)[2]), "r"((a)[3]),         \
                   "r"(b0), "r"(b1))

// ---------------- 0) weight conversion fp32 -> fp16 (both weights, one launch) ----------------
#define N4Q (3*CC*CC/4)
#define N4P (CC*CC/4)
__global__ void k_cvtw(const float* __restrict__ wq, const float* __restrict__ wp) {
    int i = blockIdx.x * 256 + threadIdx.x;
    if (i < N4Q) {
        float4 v = ((const float4*)wq)[i];
        ((__half2*)g_wqkv)[2*i]   = __floats2half2_rn(v.x, v.y);
        ((__half2*)g_wqkv)[2*i+1] = __floats2half2_rn(v.z, v.w);
    } else if (i < N4Q + N4P) {
        int j = i - N4Q;
        float4 v = ((const float4*)wp)[j];
        ((__half2*)g_wproj)[2*j]   = __floats2half2_rn(v.x, v.y);
        ((__half2*)g_wproj)[2*j+1] = __floats2half2_rn(v.z, v.w);
    }
}

// ---------------- 1) GroupNorm partial sums: 1024 blocks ----------------
__global__ void k_gnstats1(const float* __restrict__ x) {
    const int bg = blockIdx.x >> 4;
    const int sl = blockIdx.x & 15;
    const float4* p = (const float4*)(x + (size_t)bg * CPG * HH * WW) + sl * 6144;
    float s = 0.f, s2 = 0.f;
#pragma unroll
    for (int j = 0; j < 24; j++) {
        float4 v = p[j * 256 + threadIdx.x];
        s  += v.x + v.y + v.z + v.w;
        s2 += v.x*v.x + v.y*v.y + v.z*v.z + v.w*v.w;
    }
    __shared__ double ss[256], ss2[256];
    ss[threadIdx.x] = (double)s; ss2[threadIdx.x] = (double)s2;
    __syncthreads();
    for (int st = 128; st > 0; st >>= 1) {
        if (threadIdx.x < st) {
            ss[threadIdx.x]  += ss[threadIdx.x + st];
            ss2[threadIdx.x] += ss2[threadIdx.x + st];
        }
        __syncthreads();
    }
    if (threadIdx.x == 0) {
        g_part[blockIdx.x]  = ss[0];
        g_part2[blockIdx.x] = ss2[0];
    }
}

// ------- 2) finalize stats + normalize + affine + window-pack -> y[token, C] fp16 -------
__global__ void k_pack(const float* __restrict__ x,
                       const float* __restrict__ gw,
                       const float* __restrict__ gb) {
    __shared__ float sm[128 * 65];
    __shared__ float s_mean[2], s_rstd[2];
    const int c0 = blockIdx.x * 128;
    const int h  = blockIdx.y;
    const int b  = blockIdx.z;
    const int tid = threadIdx.x;

    const int g_lo = c0 / CPG;
    const int g_hi = (c0 + 127) / CPG;
    if (tid < 64) {
        const int slot = tid >> 5;
        const int g    = slot ? g_hi : g_lo;
        const int lane = tid & 31;
        const int bg   = b * 4 + g;
        double s  = (lane < 16) ? g_part[bg * 16 + lane]  : 0.0;
        double s2 = (lane < 16) ? g_part2[bg * 16 + lane] : 0.0;
#pragma unroll
        for (int o = 8; o > 0; o >>= 1) {
            s  += __shfl_down_sync(0xffffffffu, s, o);
            s2 += __shfl_down_sync(0xffffffffu, s2, o);
        }
        if (lane == 0) {
            const double cnt = (double)(CPG * HH * WW);
            double m   = s / cnt;
            double var = s2 / cnt - m * m;
            s_mean[slot] = (float)m;
            s_rstd[slot] = (float)rsqrt(var + EPSV);
        }
    }
    __syncthreads();

#pragma unroll
    for (int r = 0; r < 8; r++) {
        int i  = r * 256 + tid;
        int w4 = i & 15;
        int cl = i >> 4;
        int c  = c0 + cl;
        int gs = (c / CPG) != g_lo;
        float mu = s_mean[gs], rs = s_rstd[gs];
        float sc = rs * gw[c];
        float sh = gb[c] - mu * sc;
        float4 v = *(const float4*)(x + (((size_t)b * CC + c) * HH + h) * WW + 4 * w4);
        sm[cl * 65 + 4*w4]     = v.x * sc + sh;
        sm[cl * 65 + 4*w4 + 1] = v.y * sc + sh;
        sm[cl * 65 + 4*w4 + 2] = v.z * sc + sh;
        sm[cl * 65 + 4*w4 + 3] = v.w * sc + sh;
    }
    __syncthreads();

    const int hb = h >> 3, hs = h & 7;
#pragma unroll
    for (int it = 0; it < 4; it++) {
        int i  = it * 256 + tid;
        int c8 = i & 15;
        int w  = i >> 4;
        int n  = (b * 8 + hb) * 8 + (w >> 3);
        int s  = hs * 8 + (w & 7);
        float v[8];
#pragma unroll
        for (int j = 0; j < 8; j++) {
            int jj = (j + c8) & 7;
            v[jj] = sm[(c8 * 8 + jj) * 65 + w];
        }
        __half2 h0 = __floats2half2_rn(v[0], v[1]);
        __half2 h1 = __floats2half2_rn(v[2], v[3]);
        __half2 h2 = __floats2half2_rn(v[4], v[5]);
        __half2 h3 = __floats2half2_rn(v[6], v[7]);
        uint4 pk = make_uint4(*(uint32_t*)&h0, *(uint32_t*)&h1,
                              *(uint32_t*)&h2, *(uint32_t*)&h3);
        *(uint4*)(g_y + ((size_t)n * 64 + s) * CC + c0 + c8 * 8) = pk;
    }
}

// ============ 3) fp16 GEMM (qkv): 512 threads, 16 warps, 32x32 warp tiles (R10 config) ============
#define GEMM_SMEM (98304 + 3*32768)  // 196608
#define A_PITCH 768

__device__ __forceinline__ void load_B_chunk(const __half* __restrict__ Bw,
                                             uint32_t dst, int tid) {
#pragma unroll
    for (int j = 0; j < 4; j++) {
        int idx = j * 512 + tid;
        int n = idx >> 4, u = idx & 15;
        int phys = (u & ~7) | ((u & 7) ^ (n & 7));
        cp_async16(dst + n * 256 + (phys << 4), Bw + (size_t)n * CC + u * 8);
    }
    CP_COMMIT();
}

__global__ void __launch_bounds__(512)
k_hgemm(int N, int ntiles, int mbase) {
    extern __shared__ char smem[];
    const uint32_t sbA = smem_u32(smem);
    const uint32_t sbB = sbA + 98304;
    const int tid  = threadIdx.x;
    const int lane = tid & 31;
    const int wrp  = tid >> 5;          // 0..15
    const int wm   = (wrp & 3) * 32;    // 4 M warp-groups
    const int wn   = (wrp >> 2) * 32;   // 4 N warp-groups

    const __half* Bw = g_wqkv;
    const int rowbase = mbase + blockIdx.x * 128;
    const __half* Ab = g_y + (size_t)rowbase * CC;

#pragma unroll
    for (int j = 0; j < 12; j++) {
        int idx = j * 512 + tid;
        int m = idx / 48, u = idx - m * 48;
        int phys = (u & ~7) | ((u & 7) ^ (m & 7));
        cp_async16(sbA + m * A_PITCH + (phys << 4), Ab + (size_t)m * CC + u * 8);
    }
    CP_COMMIT();

    const int nc = ntiles * 3;
    load_B_chunk(Bw, sbB, tid);
    load_B_chunk(Bw + 128, sbB + 32768, tid);

    const int rA  = lane & 15;
    const int uHi = lane >> 4;
    const int r   = lane >> 2;
    const int cq  = lane & 3;

    float acc[2][4][4];
#pragma unroll
    for (int mi = 0; mi < 2; mi++)
#pragma unroll
        for (int ni = 0; ni < 4; ni++)
#pragma unroll
            for (int e = 0; e < 4; e++) acc[mi][ni][e] = 0.f;

    for (int nt = 0; nt < ntiles; nt++) {
#pragma unroll
        for (int kc = 0; kc < 3; kc++) {
            const int i = nt * 3 + kc;
            if (i < nc - 1) asm volatile("cp.async.wait_group 1;" ::: "memory");
            else            asm volatile("cp.async.wait_group 0;" ::: "memory");
            __syncthreads();

            if (i + 2 < nc) {
                const int nxt = i + 2;
                load_B_chunk(Bw + (size_t)((nxt / 3) * 128) * CC + (nxt % 3) * 128,
                             sbB + (uint32_t)((kc + 2) % 3) * 32768, tid);
            }

            const uint32_t bbase = sbB + (uint32_t)kc * 32768;
#pragma unroll
            for (int ks = 0; ks < 8; ks++) {
                const int ugA = kc * 16 + ks * 2 + uHi;
                const int ulB = ks * 2 + uHi;
                uint32_t af[2][4], bf[2][4];
#pragma unroll
                for (int mi = 0; mi < 2; mi++) {
                    int m = wm + mi * 16 + rA;
                    int phys = (ugA & ~7) | ((ugA & 7) ^ (m & 7));
                    LDSM4(af[mi][0], af[mi][1], af[mi][2], af[mi][3],
                          sbA + (uint32_t)(m * A_PITCH + (phys << 4)));
                }
#pragma unroll
                for (int g = 0; g < 2; g++) {
                    int n = wn + g * 16 + rA;
                    int phys = (ulB & ~7) | ((ulB & 7) ^ (n & 7));
                    LDSM4(bf[g][0], bf[g][1], bf[g][2], bf[g][3],
                          bbase + (uint32_t)(n * 256 + (phys << 4)));
                }
#pragma unroll
                for (int mi = 0; mi < 2; mi++)
#pragma unroll
                    for (int ni = 0; ni < 4; ni++)
                        MMA16(acc[mi][ni], af[mi], bf[ni >> 1][ni & 1], bf[ni >> 1][2 + (ni & 1)]);
            }
        }

#pragma unroll
        for (int mi = 0; mi < 2; mi++) {
            const int row0 = rowbase + wm + mi * 16 + r;
#pragma unroll
            for (int ni = 0; ni < 4; ni++) {
                const int col = nt * 128 + wn + ni * 8 + cq * 2;
                *(__half2*)(g_qkv + (size_t)row0 * N + col) =
                    __floats2half2_rn(acc[mi][ni][0], acc[mi][ni][1]);
                *(__half2*)(g_qkv + (size_t)(row0 + 8) * N + col) =
                    __floats2half2_rn(acc[mi][ni][2], acc[mi][ni][3]);
                acc[mi][ni][0] = acc[mi][ni][1] = acc[mi][ni][2] = acc[mi][ni][3] = 0.f;
            }
        }
    }
}

// ============ 4) fused attention + proj: 1 block = 1 window, 16 warps ============
#define ATTN_SMEM (147456 + 49152)   // 196608
#define H_PITCH 768

__global__ void __launch_bounds__(512, 1) k_attn_proj(const float* __restrict__ bias, int wofs) {
    extern __shared__ char smem[];
    const uint32_t sb  = smem_u32(smem);
    const uint32_t sbH = sb + 147456;
    const int tid  = threadIdx.x;
    const int lane = tid & 31;
    const int wrp  = tid >> 5;
    const int head = wrp >> 1;
    const int hlf  = wrp & 1;
    const int win  = wofs + blockIdx.x;

    const __half* src = g_qkv + (size_t)win * 64 * 1152;
#pragma unroll
    for (int j = 0; j < 18; j++) {
        int idx = j * 512 + tid;
        int t = idx / 144, c = idx % 144;
        cp_async16(sb + t * 2304 + ((c ^ (t & 7)) << 4), src + (size_t)t * 1152 + c * 8);
    }
    CP_COMMIT();
    asm volatile("cp.async.wait_group 0;" ::: "memory");
    __syncthreads();

    const int rA = lane & 15;
    const int hi = lane >> 4;
    const int qcb = head * 6;
    const int kcb = 48 + head * 6;
    const int vcb = 96 + head * 6;

    float S[2][8][4];
#pragma unroll
    for (int mi = 0; mi < 2; mi++)
#pragma unroll
        for (int ni = 0; ni < 8; ni++)
#pragma unroll
            for (int e = 0; e < 4; e++) S[mi][ni][e] = 0.f;

#pragma unroll
    for (int kt = 0; kt < 3; kt++) {
        uint32_t aq[2][4];
#pragma unroll
        for (int mi = 0; mi < 2; mi++) {
            int m = hlf * 32 + mi * 16 + rA;
            uint32_t a = sb + m * 2304 + (((qcb + kt * 2 + hi) ^ (m & 7)) << 4);
            LDSM4(aq[mi][0], aq[mi][1], aq[mi][2], aq[mi][3], a);
        }
#pragma unroll
        for (int g = 0; g < 4; g++) {
            int n = g * 16 + rA;
            uint32_t a = sb + n * 2304 + (((kcb + kt * 2 + hi) ^ (n & 7)) << 4);
            uint32_t b0, b1, b2, b3;
            LDSM4(b0, b1, b2, b3, a);
#pragma unroll
            for (int mi = 0; mi < 2; mi++) {
                MMA16(S[mi][2*g],     aq[mi], b0, b2);
                MMA16(S[mi][2*g + 1], aq[mi], b1, b3);
            }
        }
    }

    const float cs = 0.14433756729740643f * 1.4426950408889634f;
    float mx[2][2];
#pragma unroll
    for (int mi = 0; mi < 2; mi++) { mx[mi][0] = -1e30f; mx[mi][1] = -1e30f; }
#pragma unroll
    for (int mi = 0; mi < 2; mi++)
#pragma unroll
        for (int ni = 0; ni < 8; ni++) {
            mx[mi][0] = fmaxf(mx[mi][0], fmaxf(S[mi][ni][0], S[mi][ni][1]));
            mx[mi][1] = fmaxf(mx[mi][1], fmaxf(S[mi][ni][2], S[mi][ni][3]));
        }
#pragma unroll
    for (int mi = 0; mi < 2; mi++)
#pragma unroll
        for (int e = 0; e < 2; e++) {
            mx[mi][e] = fmaxf(mx[mi][e], __shfl_xor_sync(0xffffffffu, mx[mi][e], 1));
            mx[mi][e] = fmaxf(mx[mi][e], __shfl_xor_sync(0xffffffffu, mx[mi][e], 2));
        }

    uint32_t P[2][4][4];
    float sum[2][2] = {{0.f, 0.f}, {0.f, 0.f}};
#pragma unroll
    for (int mi = 0; mi < 2; mi++)
#pragma unroll
        for (int kt = 0; kt < 4; kt++)
#pragma unroll
            for (int q = 0; q < 2; q++) {
                const int ni = 2 * kt + q;
                float e0 = exp2f((S[mi][ni][0] - mx[mi][0]) * cs);
                float e1 = exp2f((S[mi][ni][1] - mx[mi][0]) * cs);
                float e2 = exp2f((S[mi][ni][2] - mx[mi][1]) * cs);
                float e3 = exp2f((S[mi][ni][3] - mx[mi][1]) * cs);
                sum[mi][0] += e0 + e1;
                sum[mi][1] += e2 + e3;
                __half2 h0 = __floats2half2_rn(e0, e1);
                __half2 h1 = __floats2half2_rn(e2, e3);
                P[mi][kt][2*q]     = *(uint32_t*)&h0;
                P[mi][kt][2*q + 1] = *(uint32_t*)&h1;
            }
#pragma unroll
    for (int mi = 0; mi < 2; mi++)
#pragma unroll
        for (int e = 0; e < 2; e++) {
            sum[mi][e] += __shfl_xor_sync(0xffffffffu, sum[mi][e], 1);
            sum[mi][e] += __shfl_xor_sync(0xffffffffu, sum[mi][e], 2);
        }

    float O[2][6][4];
#pragma unroll
    for (int mi = 0; mi < 2; mi++)
#pragma unroll
        for (int ni = 0; ni < 6; ni++)
#pragma unroll
            for (int e = 0; e < 4; e++) O[mi][ni][e] = 0.f;

#pragma unroll
    for (int kt = 0; kt < 4; kt++) {
#pragma unroll
        for (int p = 0; p < 3; p++) {
            int t = kt * 16 + rA;
            uint32_t a = sb + t * 2304 + (((vcb + 2*p + hi) ^ (t & 7)) << 4);
            uint32_t v0, v1, v2, v3;
            LDSM4T(v0, v1, v2, v3, a);
#pragma unroll
            for (int mi = 0; mi < 2; mi++) {
                MMA16(O[mi][2*p],     P[mi][kt], v0, v1);
                MMA16(O[mi][2*p + 1], P[mi][kt], v2, v3);
            }
        }
    }

    const int r  = lane >> 2;
    const int cq = lane & 3;
#pragma unroll
    for (int mi = 0; mi < 2; mi++) {
        const float i0 = 1.f / sum[mi][0];
        const float i1 = 1.f / sum[mi][1];
#pragma unroll
        for (int ni = 0; ni < 6; ni++) {
            const int u = head * 6 + ni;
            const int m0 = hlf * 32 + mi * 16 + r;
            const int m1 = m0 + 8;
            __half2 h0 = __floats2half2_rn(O[mi][ni][0] * i0, O[mi][ni][1] * i0);
            __half2 h1 = __floats2half2_rn(O[mi][ni][2] * i1, O[mi][ni][3] * i1);
            int ph0 = (u & ~7) | ((u & 7) ^ (m0 & 7));
            int ph1 = (u & ~7) | ((u & 7) ^ (m1 & 7));
            *(uint32_t*)(smem + 147456 + m0 * H_PITCH + (ph0 << 4) + cq * 4) = *(uint32_t*)&h0;
            *(uint32_t*)(smem + 147456 + m1 * H_PITCH + (ph1 << 4) + cq * 4) = *(uint32_t*)&h1;
        }
    }
    __syncthreads();

    const int wm2 = (wrp & 1) * 32;
    const int wn2 = (wrp >> 1) * 48;
    const __half* Wp = g_wproj;

#define LOAD_W(cI, bI)                                                          \
    {                                                                           \
        const uint32_t dstw = sb + (uint32_t)(bI) * 49152;                      \
        _Pragma("unroll")                                                       \
        for (int j = 0; j < 6; j++) {                                           \
            int idx = j * 512 + tid;                                            \
            int n = idx >> 3, u = idx & 7;                                      \
            cp_async16(dstw + n * 128 + ((u ^ (n & 7)) << 4),                   \
                       Wp + (size_t)n * CC + (cI) * 64 + u * 8);                \
        }                                                                       \
        CP_COMMIT();                                                            \
    }

    LOAD_W(0, 0);
    LOAD_W(1, 1);

    float acc2[2][6][4];
#pragma unroll
    for (int mi = 0; mi < 2; mi++)
#pragma unroll
        for (int ni = 0; ni < 6; ni++)
#pragma unroll
            for (int e = 0; e < 4; e++) acc2[mi][ni][e] = 0.f;

    for (int c = 0; c < 6; c++) {
        if (c < 5) asm volatile("cp.async.wait_group 1;" ::: "memory");
        else       asm volatile("cp.async.wait_group 0;" ::: "memory");
        __syncthreads();

        if (c + 2 < 6) LOAD_W(c + 2, (c + 2) % 3);

        const uint32_t wbase = sb + (uint32_t)(c % 3) * 49152;
#pragma unroll
        for (int ks = 0; ks < 4; ks++) {
            const int ugA = c * 8 + ks * 2 + hi;
            const int ulB = ks * 2 + hi;
            uint32_t af[2][4], bf[3][4];
#pragma unroll
            for (int mi = 0; mi < 2; mi++) {
                int m = wm2 + mi * 16 + rA;
                int phys = (ugA & ~7) | ((ugA & 7) ^ (m & 7));
                LDSM4(af[mi][0], af[mi][1], af[mi][2], af[mi][3],
                      sbH + (uint32_t)(m * H_PITCH + (phys << 4)));
            }
#pragma unroll
            for (int g = 0; g < 3; g++) {
                int n = wn2 + g * 16 + rA;
                int phys = ulB ^ (n & 7);
                LDSM4(bf[g][0], bf[g][1], bf[g][2], bf[g][3],
                      wbase + (uint32_t)(n * 128 + (phys << 4)));
            }
#pragma unroll
            for (int mi = 0; mi < 2; mi++)
#pragma unroll
                for (int g = 0; g < 3; g++) {
                    MMA16(acc2[mi][2*g],     af[mi], bf[g][0], bf[g][2]);
                    MMA16(acc2[mi][2*g + 1], af[mi], bf[g][1], bf[g][3]);
                }
        }
    }

    __half* dst = g_o + (size_t)win * 64 * CC;
#pragma unroll
    for (int mi = 0; mi < 2; mi++) {
        const int m0 = wm2 + mi * 16 + r;
#pragma unroll
        for (int ni = 0; ni < 6; ni++) {
            const int col = wn2 + ni * 8 + 2 * cq;
            float b0 = bias[col], b1 = bias[col + 1];
            *(__half2*)(dst + (size_t)m0 * CC + col) =
                __floats2half2_rn(acc2[mi][ni][0] + b0, acc2[mi][ni][1] + b1);
            *(__half2*)(dst + (size_t)(m0 + 8) * CC + col) =
                __floats2half2_rn(acc2[mi][ni][2] + b0, acc2[mi][ni][3] + b1);
        }
    }
}

// --------- 6) un-window + residual:  g_o[token,C] fp16 -> out(B,C,H,W) += x ---------
__global__ void k_unpack(const float* __restrict__ x, float* __restrict__ out, int b0) {
    __shared__ float sm[128 * 65];
    const int c0 = blockIdx.x * 128;
    const int h  = blockIdx.y;
    const int b  = b0 + blockIdx.z;
    const int tid = threadIdx.x;
    const int hb = h >> 3, hs = h & 7;
#pragma unroll
    for (int it = 0; it < 4; it++) {
        int i  = it * 256 + tid;
        int c8 = i & 15;
        int w  = i >> 4;
        int n  = (b * 8 + hb) * 8 + (w >> 3);
        int s  = hs * 8 + (w & 7);
        uint4 pk = *(const uint4*)(g_o + ((size_t)n * 64 + s) * CC + c0 + c8 * 8);
        const __half2* hp = (const __half2*)&pk;
#pragma unroll
        for (int j = 0; j < 4; j++) {
            float2 fv = __half22float2(hp[j]);
            sm[(c8 * 8 + 2*j)     * 65 + w] = fv.x;
            sm[(c8 * 8 + 2*j + 1) * 65 + w] = fv.y;
        }
    }
    __syncthreads();
#pragma unroll
    for (int r = 0; r < 8; r++) {
        int i  = r * 256 + tid;
        int w4 = i & 15;
        int cl = i >> 4;
        size_t gi = (((size_t)b * CC + c0 + cl) * HH + h) * WW + 4 * w4;
        float4 xv = *(const float4*)(x + gi);
        float4 ov;
        ov.x = sm[cl * 65 + 4*w4]     + xv.x;
        ov.y = sm[cl * 65 + 4*w4 + 1] + xv.y;
        ov.z = sm[cl * 65 + 4*w4 + 2] + xv.z;
        ov.w = sm[cl * 65 + 4*w4 + 3] + xv.w;
        *(float4*)(out + gi) = ov;
    }
}

// --------------------------------- launch ---------------------------------
extern "C" void kernel_launch(void* const* d_in, const int* in_sizes, int n_in,
                              void* d_out, int out_size) {
    const float* x     = (const float*)d_in[0];
    const float* gw    = (const float*)d_in[1];
    const float* gb    = (const float*)d_in[2];
    const float* wqkv  = (const float*)d_in[3];
    const float* wproj = (const float*)d_in[4];
    const float* bproj = (const float*)d_in[5];
    float* out = (float*)d_out;

    static cudaStream_t s2 = nullptr;
    static cudaEvent_t evFork, evCvtw, evG0, evG1, evA0, evA1;
    if (!s2) {
        cudaStreamCreateWithFlags(&s2, cudaStreamNonBlocking);
        cudaEventCreateWithFlags(&evFork, cudaEventDisableTiming);
        cudaEventCreateWithFlags(&evCvtw, cudaEventDisableTiming);
        cudaEventCreateWithFlags(&evG0,   cudaEventDisableTiming);
        cudaEventCreateWithFlags(&evG1,   cudaEventDisableTiming);
        cudaEventCreateWithFlags(&evA0,   cudaEventDisableTiming);
        cudaEventCreateWithFlags(&evA1,   cudaEventDisableTiming);
        cudaFuncSetAttribute(k_hgemm,     cudaFuncAttributeMaxDynamicSharedMemorySize, GEMM_SMEM);
        cudaFuncSetAttribute(k_attn_proj, cudaFuncAttributeMaxDynamicSharedMemorySize, ATTN_SMEM);
    }

    // fork: cvtw on s2, gnstats1+pack on default
    cudaEventRecord(evFork, 0);
    cudaStreamWaitEvent(s2, evFork, 0);
    k_cvtw<<<(N4Q + N4P + 255)/256, 256, 0, s2>>>(wqkv, wproj);
    cudaEventRecord(evCvtw, s2);

    k_gnstats1<<<BB * NGROUPS * 16, 256>>>(x);
    k_pack<<<dim3(3, HH, BB), 256>>>(x, gw, gb);

    // hgemm halves on default (needs cvtw)
    cudaStreamWaitEvent(0, evCvtw, 0);
    k_hgemm<<<256, 512, GEMM_SMEM>>>(3 * CC, 9, 0);
    cudaEventRecord(evG0, 0);
    k_hgemm<<<256, 512, GEMM_SMEM>>>(3 * CC, 9, 32768);
    cudaEventRecord(evG1, 0);

    // attn halves on s2: attn0 overlaps hgemm1
    cudaStreamWaitEvent(s2, evG0, 0);
    k_attn_proj<<<512, 512, ATTN_SMEM, s2>>>(bproj, 0);
    cudaEventRecord(evA0, s2);
    cudaStreamWaitEvent(s2, evG1, 0);
    k_attn_proj<<<512, 512, ATTN_SMEM, s2>>>(bproj, 512);
    cudaEventRecord(evA1, s2);

    // unpack halves on default: unpack0 overlaps attn1
    cudaStreamWaitEvent(0, evA0, 0);
    k_unpack<<<dim3(3, HH, 8), 256>>>(x, out, 0);
    cudaStreamWaitEvent(0, evA1, 0);
    k_unpack<<<dim3(3, HH, 8), 256>>>(x, out, 8);
}

// round 14
// speedup vs baseline: 1.0647x; 1.0248x over previous
#include <cuda_runtime.h>
#include <cuda_fp16.h>
#include <math.h>
#include <stdint.h>

#define BB 16
#define CC 384
#define HH 64
#define WW 64
#define NHEADS 8
#define HD 48
#define NGROUPS 4
#define CPG 96
#define NTOK (BB*HH*WW)     // 65536 tokens
#define EPSV 1e-5

// ---------------- scratch (static device globals; no allocations) ----------------
__device__ double g_part[BB*NGROUPS*16];
__device__ double g_part2[BB*NGROUPS*16];
__device__ __half g_y[(size_t)NTOK*CC];       // normalized windowed tokens (fp16, GEMM A)
__device__ __half g_qkv[(size_t)NTOK*3*CC];   // qkv projections (fp16)
__device__ __half g_wqkv[(size_t)3*CC*CC];    // fp16 weights
__device__ __half g_wproj[(size_t)CC*CC];

// ==================== PTX helpers ====================
__device__ __forceinline__ uint32_t smem_u32(const void* p) {
    uint32_t a;
    asm("{ .reg .u64 t; cvta.to.shared.u64 t, %1; cvt.u32.u64 %0, t; }" : "=r"(a) : "l"(p));
    return a;
}
__device__ __forceinline__ void cp_async16(uint32_t dst, const void* src) {
    asm volatile("cp.async.cg.shared.global [%0], [%1], 16;" :: "r"(dst), "l"(src) : "memory");
}
#define CP_COMMIT() asm volatile("cp.async.commit_group;" ::: "memory")

#define LDSM4(r0, r1, r2, r3, a)                                               \
    asm volatile("ldmatrix.sync.aligned.m8n8.x4.shared.b16 {%0,%1,%2,%3}, [%4];"\
                 : "=r"(r0), "=r"(r1), "=r"(r2), "=r"(r3) : "r"(a))

#define LDSM4T(r0, r1, r2, r3, a)                                              \
    asm volatile("ldmatrix.sync.aligned.m8n8.x4.trans.shared.b16 {%0,%1,%2,%3}, [%4];"\
                 : "=r"(r0), "=r"(r1), "=r"(r2), "=r"(r3) : "r"(a))

#define MMA16(d, a, b0, b1)                                                    \
    asm volatile("mma.sync.aligned.m16n8k16.row.col.f32.f16.f16.f32 "          \
                 "{%0,%1,%2,%3}, {%4,%5,%6,%7}, {%8,%9}, {%0,%1,%2,%3};"       \
                 : "+f"((d)[0]), "+f"((d)[1]), "+f"((d)[2]), "+f"((d)[3])      \
                 : "r"((a)[0]), "r"((a)[1]), "r"((a)[2]), "r"((a)[3]),         \
                   "r"(b0), "r"(b1))

// ---------------- 0) weight conversion fp32 -> fp16 (both weights, one launch) ----------------
#define N4Q (3*CC*CC/4)
#define N4P (CC*CC/4)
__global__ void k_cvtw(const float* __restrict__ wq, const float* __restrict__ wp) {
    int i = blockIdx.x * 256 + threadIdx.x;
    if (i < N4Q) {
        float4 v = ((const float4*)wq)[i];
        ((__half2*)g_wqkv)[2*i]   = __floats2half2_rn(v.x, v.y);
        ((__half2*)g_wqkv)[2*i+1] = __floats2half2_rn(v.z, v.w);
    } else if (i < N4Q + N4P) {
        int j = i - N4Q;
        float4 v = ((const float4*)wp)[j];
        ((__half2*)g_wproj)[2*j]   = __floats2half2_rn(v.x, v.y);
        ((__half2*)g_wproj)[2*j+1] = __floats2half2_rn(v.z, v.w);
    }
}

// ---------------- 1) GroupNorm partial sums: 1024 blocks ----------------
__global__ void k_gnstats1(const float* __restrict__ x) {
    const int bg = blockIdx.x >> 4;
    const int sl = blockIdx.x & 15;
    const float4* p = (const float4*)(x + (size_t)bg * CPG * HH * WW) + sl * 6144;
    float s = 0.f, s2 = 0.f;
#pragma unroll
    for (int j = 0; j < 24; j++) {
        float4 v = p[j * 256 + threadIdx.x];
        s  += v.x + v.y + v.z + v.w;
        s2 += v.x*v.x + v.y*v.y + v.z*v.z + v.w*v.w;
    }
    __shared__ double ss[256], ss2[256];
    ss[threadIdx.x] = (double)s; ss2[threadIdx.x] = (double)s2;
    __syncthreads();
    for (int st = 128; st > 0; st >>= 1) {
        if (threadIdx.x < st) {
            ss[threadIdx.x]  += ss[threadIdx.x + st];
            ss2[threadIdx.x] += ss2[threadIdx.x + st];
        }
        __syncthreads();
    }
    if (threadIdx.x == 0) {
        g_part[blockIdx.x]  = ss[0];
        g_part2[blockIdx.x] = ss2[0];
    }
}

// ------- 2) finalize stats + normalize + affine + window-pack -> y[token, C] fp16 -------
__global__ void k_pack(const float* __restrict__ x,
                       const float* __restrict__ gw,
                       const float* __restrict__ gb) {
    __shared__ float sm[128 * 65];
    __shared__ float s_mean[2], s_rstd[2];
    const int c0 = blockIdx.x * 128;
    const int h  = blockIdx.y;
    const int b  = blockIdx.z;
    const int tid = threadIdx.x;

    const int g_lo = c0 / CPG;
    const int g_hi = (c0 + 127) / CPG;
    if (tid < 64) {
        const int slot = tid >> 5;
        const int g    = slot ? g_hi : g_lo;
        const int lane = tid & 31;
        const int bg   = b * 4 + g;
        double s  = (lane < 16) ? g_part[bg * 16 + lane]  : 0.0;
        double s2 = (lane < 16) ? g_part2[bg * 16 + lane] : 0.0;
#pragma unroll
        for (int o = 8; o > 0; o >>= 1) {
            s  += __shfl_down_sync(0xffffffffu, s, o);
            s2 += __shfl_down_sync(0xffffffffu, s2, o);
        }
        if (lane == 0) {
            const double cnt = (double)(CPG * HH * WW);
            double m   = s / cnt;
            double var = s2 / cnt - m * m;
            s_mean[slot] = (float)m;
            s_rstd[slot] = (float)rsqrt(var + EPSV);
        }
    }
    __syncthreads();

#pragma unroll
    for (int r = 0; r < 8; r++) {
        int i  = r * 256 + tid;
        int w4 = i & 15;
        int cl = i >> 4;
        int c  = c0 + cl;
        int gs = (c / CPG) != g_lo;
        float mu = s_mean[gs], rs = s_rstd[gs];
        float sc = rs * gw[c];
        float sh = gb[c] - mu * sc;
        float4 v = *(const float4*)(x + (((size_t)b * CC + c) * HH + h) * WW + 4 * w4);
        sm[cl * 65 + 4*w4]     = v.x * sc + sh;
        sm[cl * 65 + 4*w4 + 1] = v.y * sc + sh;
        sm[cl * 65 + 4*w4 + 2] = v.z * sc + sh;
        sm[cl * 65 + 4*w4 + 3] = v.w * sc + sh;
    }
    __syncthreads();

    const int hb = h >> 3, hs = h & 7;
#pragma unroll
    for (int it = 0; it < 4; it++) {
        int i  = it * 256 + tid;
        int c8 = i & 15;
        int w  = i >> 4;
        int n  = (b * 8 + hb) * 8 + (w >> 3);
        int s  = hs * 8 + (w & 7);
        float v[8];
#pragma unroll
        for (int j = 0; j < 8; j++) {
            int jj = (j + c8) & 7;
            v[jj] = sm[(c8 * 8 + jj) * 65 + w];
        }
        __half2 h0 = __floats2half2_rn(v[0], v[1]);
        __half2 h1 = __floats2half2_rn(v[2], v[3]);
        __half2 h2 = __floats2half2_rn(v[4], v[5]);
        __half2 h3 = __floats2half2_rn(v[6], v[7]);
        uint4 pk = make_uint4(*(uint32_t*)&h0, *(uint32_t*)&h1,
                              *(uint32_t*)&h2, *(uint32_t*)&h3);
        *(uint4*)(g_y + ((size_t)n * 64 + s) * CC + c0 + c8 * 8) = pk;
    }
}

// ============ 3) fp16 GEMM (qkv): 512 threads, 16 warps, 32x32 warp tiles ============
#define GEMM_SMEM (98304 + 3*32768)  // 196608
#define A_PITCH 768

__device__ __forceinline__ void load_B_chunk(const __half* __restrict__ Bw,
                                             uint32_t dst, int tid) {
#pragma unroll
    for (int j = 0; j < 4; j++) {
        int idx = j * 512 + tid;
        int n = idx >> 4, u = idx & 15;
        int phys = (u & ~7) | ((u & 7) ^ (n & 7));
        cp_async16(dst + n * 256 + (phys << 4), Bw + (size_t)n * CC + u * 8);
    }
    CP_COMMIT();
}

__global__ void __launch_bounds__(512)
k_hgemm(int N, int ntiles, int mbase) {
    extern __shared__ char smem[];
    const uint32_t sbA = smem_u32(smem);
    const uint32_t sbB = sbA + 98304;
    const int tid  = threadIdx.x;
    const int lane = tid & 31;
    const int wrp  = tid >> 5;
    const int wm   = (wrp & 3) * 32;
    const int wn   = (wrp >> 2) * 32;

    const __half* Bw = g_wqkv;
    const int rowbase = mbase + blockIdx.x * 128;
    const __half* Ab = g_y + (size_t)rowbase * CC;

#pragma unroll
    for (int j = 0; j < 12; j++) {
        int idx = j * 512 + tid;
        int m = idx / 48, u = idx - m * 48;
        int phys = (u & ~7) | ((u & 7) ^ (m & 7));
        cp_async16(sbA + m * A_PITCH + (phys << 4), Ab + (size_t)m * CC + u * 8);
    }
    CP_COMMIT();

    const int nc = ntiles * 3;
    load_B_chunk(Bw, sbB, tid);
    load_B_chunk(Bw + 128, sbB + 32768, tid);

    const int rA  = lane & 15;
    const int uHi = lane >> 4;
    const int r   = lane >> 2;
    const int cq  = lane & 3;

    float acc[2][4][4];
#pragma unroll
    for (int mi = 0; mi < 2; mi++)
#pragma unroll
        for (int ni = 0; ni < 4; ni++)
#pragma unroll
            for (int e = 0; e < 4; e++) acc[mi][ni][e] = 0.f;

    for (int nt = 0; nt < ntiles; nt++) {
#pragma unroll
        for (int kc = 0; kc < 3; kc++) {
            const int i = nt * 3 + kc;
            if (i < nc - 1) asm volatile("cp.async.wait_group 1;" ::: "memory");
            else            asm volatile("cp.async.wait_group 0;" ::: "memory");
            __syncthreads();

            if (i + 2 < nc) {
                const int nxt = i + 2;
                load_B_chunk(Bw + (size_t)((nxt / 3) * 128) * CC + (nxt % 3) * 128,
                             sbB + (uint32_t)((kc + 2) % 3) * 32768, tid);
            }

            const uint32_t bbase = sbB + (uint32_t)kc * 32768;
#pragma unroll
            for (int ks = 0; ks < 8; ks++) {
                const int ugA = kc * 16 + ks * 2 + uHi;
                const int ulB = ks * 2 + uHi;
                uint32_t af[2][4], bf[2][4];
#pragma unroll
                for (int mi = 0; mi < 2; mi++) {
                    int m = wm + mi * 16 + rA;
                    int phys = (ugA & ~7) | ((ugA & 7) ^ (m & 7));
                    LDSM4(af[mi][0], af[mi][1], af[mi][2], af[mi][3],
                          sbA + (uint32_t)(m * A_PITCH + (phys << 4)));
                }
#pragma unroll
                for (int g = 0; g < 2; g++) {
                    int n = wn + g * 16 + rA;
                    int phys = (ulB & ~7) | ((ulB & 7) ^ (n & 7));
                    LDSM4(bf[g][0], bf[g][1], bf[g][2], bf[g][3],
                          bbase + (uint32_t)(n * 256 + (phys << 4)));
                }
#pragma unroll
                for (int mi = 0; mi < 2; mi++)
#pragma unroll
                    for (int ni = 0; ni < 4; ni++)
                        MMA16(acc[mi][ni], af[mi], bf[ni >> 1][ni & 1], bf[ni >> 1][2 + (ni & 1)]);
            }
        }

#pragma unroll
        for (int mi = 0; mi < 2; mi++) {
            const int row0 = rowbase + wm + mi * 16 + r;
#pragma unroll
            for (int ni = 0; ni < 4; ni++) {
                const int col = nt * 128 + wn + ni * 8 + cq * 2;
                *(__half2*)(g_qkv + (size_t)row0 * N + col) =
                    __floats2half2_rn(acc[mi][ni][0], acc[mi][ni][1]);
                *(__half2*)(g_qkv + (size_t)(row0 + 8) * N + col) =
                    __floats2half2_rn(acc[mi][ni][2], acc[mi][ni][3]);
                acc[mi][ni][0] = acc[mi][ni][1] = acc[mi][ni][2] = acc[mi][ni][3] = 0.f;
            }
        }
    }
}

// ============ 4) fused attention + proj + un-window + residual ============
// Epilogue writes out(B,C,H,W) = proj + bias + x directly (no g_o, no unpack).
#define ATTN_SMEM (147456 + 49152)   // 196608
#define H_PITCH 768

__global__ void __launch_bounds__(512, 1)
k_attn_proj(const float* __restrict__ bias, const float* __restrict__ x,
            float* __restrict__ out, int wofs) {
    extern __shared__ char smem[];
    const uint32_t sb  = smem_u32(smem);
    const uint32_t sbH = sb + 147456;
    const int tid  = threadIdx.x;
    const int lane = tid & 31;
    const int wrp  = tid >> 5;
    const int head = wrp >> 1;
    const int hlf  = wrp & 1;
    const int win  = wofs + blockIdx.x;

    const __half* src = g_qkv + (size_t)win * 64 * 1152;
#pragma unroll
    for (int j = 0; j < 18; j++) {
        int idx = j * 512 + tid;
        int t = idx / 144, c = idx % 144;
        cp_async16(sb + t * 2304 + ((c ^ (t & 7)) << 4), src + (size_t)t * 1152 + c * 8);
    }
    CP_COMMIT();
    asm volatile("cp.async.wait_group 0;" ::: "memory");
    __syncthreads();

    const int rA = lane & 15;
    const int hi = lane >> 4;
    const int qcb = head * 6;
    const int kcb = 48 + head * 6;
    const int vcb = 96 + head * 6;

    float S[2][8][4];
#pragma unroll
    for (int mi = 0; mi < 2; mi++)
#pragma unroll
        for (int ni = 0; ni < 8; ni++)
#pragma unroll
            for (int e = 0; e < 4; e++) S[mi][ni][e] = 0.f;

#pragma unroll
    for (int kt = 0; kt < 3; kt++) {
        uint32_t aq[2][4];
#pragma unroll
        for (int mi = 0; mi < 2; mi++) {
            int m = hlf * 32 + mi * 16 + rA;
            uint32_t a = sb + m * 2304 + (((qcb + kt * 2 + hi) ^ (m & 7)) << 4);
            LDSM4(aq[mi][0], aq[mi][1], aq[mi][2], aq[mi][3], a);
        }
#pragma unroll
        for (int g = 0; g < 4; g++) {
            int n = g * 16 + rA;
            uint32_t a = sb + n * 2304 + (((kcb + kt * 2 + hi) ^ (n & 7)) << 4);
            uint32_t b0, b1, b2, b3;
            LDSM4(b0, b1, b2, b3, a);
#pragma unroll
            for (int mi = 0; mi < 2; mi++) {
                MMA16(S[mi][2*g],     aq[mi], b0, b2);
                MMA16(S[mi][2*g + 1], aq[mi], b1, b3);
            }
        }
    }

    const float cs = 0.14433756729740643f * 1.4426950408889634f;
    float mx[2][2];
#pragma unroll
    for (int mi = 0; mi < 2; mi++) { mx[mi][0] = -1e30f; mx[mi][1] = -1e30f; }
#pragma unroll
    for (int mi = 0; mi < 2; mi++)
#pragma unroll
        for (int ni = 0; ni < 8; ni++) {
            mx[mi][0] = fmaxf(mx[mi][0], fmaxf(S[mi][ni][0], S[mi][ni][1]));
            mx[mi][1] = fmaxf(mx[mi][1], fmaxf(S[mi][ni][2], S[mi][ni][3]));
        }
#pragma unroll
    for (int mi = 0; mi < 2; mi++)
#pragma unroll
        for (int e = 0; e < 2; e++) {
            mx[mi][e] = fmaxf(mx[mi][e], __shfl_xor_sync(0xffffffffu, mx[mi][e], 1));
            mx[mi][e] = fmaxf(mx[mi][e], __shfl_xor_sync(0xffffffffu, mx[mi][e], 2));
        }

    uint32_t P[2][4][4];
    float sum[2][2] = {{0.f, 0.f}, {0.f, 0.f}};
#pragma unroll
    for (int mi = 0; mi < 2; mi++)
#pragma unroll
        for (int kt = 0; kt < 4; kt++)
#pragma unroll
            for (int q = 0; q < 2; q++) {
                const int ni = 2 * kt + q;
                float e0 = exp2f((S[mi][ni][0] - mx[mi][0]) * cs);
                float e1 = exp2f((S[mi][ni][1] - mx[mi][0]) * cs);
                float e2 = exp2f((S[mi][ni][2] - mx[mi][1]) * cs);
                float e3 = exp2f((S[mi][ni][3] - mx[mi][1]) * cs);
                sum[mi][0] += e0 + e1;
                sum[mi][1] += e2 + e3;
                __half2 h0 = __floats2half2_rn(e0, e1);
                __half2 h1 = __floats2half2_rn(e2, e3);
                P[mi][kt][2*q]     = *(uint32_t*)&h0;
                P[mi][kt][2*q + 1] = *(uint32_t*)&h1;
            }
#pragma unroll
    for (int mi = 0; mi < 2; mi++)
#pragma unroll
        for (int e = 0; e < 2; e++) {
            sum[mi][e] += __shfl_xor_sync(0xffffffffu, sum[mi][e], 1);
            sum[mi][e] += __shfl_xor_sync(0xffffffffu, sum[mi][e], 2);
        }

    float O[2][6][4];
#pragma unroll
    for (int mi = 0; mi < 2; mi++)
#pragma unroll
        for (int ni = 0; ni < 6; ni++)
#pragma unroll
            for (int e = 0; e < 4; e++) O[mi][ni][e] = 0.f;

#pragma unroll
    for (int kt = 0; kt < 4; kt++) {
#pragma unroll
        for (int p = 0; p < 3; p++) {
            int t = kt * 16 + rA;
            uint32_t a = sb + t * 2304 + (((vcb + 2*p + hi) ^ (t & 7)) << 4);
            uint32_t v0, v1, v2, v3;
            LDSM4T(v0, v1, v2, v3, a);
#pragma unroll
            for (int mi = 0; mi < 2; mi++) {
                MMA16(O[mi][2*p],     P[mi][kt], v0, v1);
                MMA16(O[mi][2*p + 1], P[mi][kt], v2, v3);
            }
        }
    }

    // ---- store h = O/rowsum into smem h tile ----
    const int r  = lane >> 2;
    const int cq = lane & 3;
#pragma unroll
    for (int mi = 0; mi < 2; mi++) {
        const float i0 = 1.f / sum[mi][0];
        const float i1 = 1.f / sum[mi][1];
#pragma unroll
        for (int ni = 0; ni < 6; ni++) {
            const int u = head * 6 + ni;
            const int m0 = hlf * 32 + mi * 16 + r;
            const int m1 = m0 + 8;
            __half2 h0 = __floats2half2_rn(O[mi][ni][0] * i0, O[mi][ni][1] * i0);
            __half2 h1 = __floats2half2_rn(O[mi][ni][2] * i1, O[mi][ni][3] * i1);
            int ph0 = (u & ~7) | ((u & 7) ^ (m0 & 7));
            int ph1 = (u & ~7) | ((u & 7) ^ (m1 & 7));
            *(uint32_t*)(smem + 147456 + m0 * H_PITCH + (ph0 << 4) + cq * 4) = *(uint32_t*)&h0;
            *(uint32_t*)(smem + 147456 + m1 * H_PITCH + (ph1 << 4) + cq * 4) = *(uint32_t*)&h1;
        }
    }
    __syncthreads();

    // ---- proj: C[64,384] = h @ w_proj^T ----
    const int wm2 = (wrp & 1) * 32;
    const int wn2 = (wrp >> 1) * 48;
    const __half* Wp = g_wproj;

#define LOAD_W(cI, bI)                                                          \
    {                                                                           \
        const uint32_t dstw = sb + (uint32_t)(bI) * 49152;                      \
        _Pragma("unroll")                                                       \
        for (int j = 0; j < 6; j++) {                                           \
            int idx = j * 512 + tid;                                            \
            int n = idx >> 3, u = idx & 7;                                      \
            cp_async16(dstw + n * 128 + ((u ^ (n & 7)) << 4),                   \
                       Wp + (size_t)n * CC + (cI) * 64 + u * 8);                \
        }                                                                       \
        CP_COMMIT();                                                            \
    }

    LOAD_W(0, 0);
    LOAD_W(1, 1);

    float acc2[2][6][4];
#pragma unroll
    for (int mi = 0; mi < 2; mi++)
#pragma unroll
        for (int ni = 0; ni < 6; ni++)
#pragma unroll
            for (int e = 0; e < 4; e++) acc2[mi][ni][e] = 0.f;

    for (int c = 0; c < 6; c++) {
        if (c < 5) asm volatile("cp.async.wait_group 1;" ::: "memory");
        else       asm volatile("cp.async.wait_group 0;" ::: "memory");
        __syncthreads();

        if (c + 2 < 6) LOAD_W(c + 2, (c + 2) % 3);

        const uint32_t wbase = sb + (uint32_t)(c % 3) * 49152;
#pragma unroll
        for (int ks = 0; ks < 4; ks++) {
            const int ugA = c * 8 + ks * 2 + hi;
            const int ulB = ks * 2 + hi;
            uint32_t af[2][4], bf[3][4];
#pragma unroll
            for (int mi = 0; mi < 2; mi++) {
                int m = wm2 + mi * 16 + rA;
                int phys = (ugA & ~7) | ((ugA & 7) ^ (m & 7));
                LDSM4(af[mi][0], af[mi][1], af[mi][2], af[mi][3],
                      sbH + (uint32_t)(m * H_PITCH + (phys << 4)));
            }
#pragma unroll
            for (int g = 0; g < 3; g++) {
                int n = wn2 + g * 16 + rA;
                int phys = ulB ^ (n & 7);
                LDSM4(bf[g][0], bf[g][1], bf[g][2], bf[g][3],
                      wbase + (uint32_t)(n * 128 + (phys << 4)));
            }
#pragma unroll
            for (int mi = 0; mi < 2; mi++)
#pragma unroll
                for (int g = 0; g < 3; g++) {
                    MMA16(acc2[mi][2*g],     af[mi], bf[g][0], bf[g][2]);
                    MMA16(acc2[mi][2*g + 1], af[mi], bf[g][1], bf[g][3]);
                }
        }
    }

    // ---- epilogue: write out(B,C,H,W) = acc + bias + x (residual) directly ----
    const int b  = win >> 6;
    const int hb = (win >> 3) & 7;
    const int wb = win & 7;
#pragma unroll
    for (int mi = 0; mi < 2; mi++) {
        const int s0 = wm2 + mi * 16 + r;            // token 0..55
        const int h0 = hb * 8 + (s0 >> 3);
        const int w0 = wb * 8 + (s0 & 7);
#pragma unroll
        for (int ni = 0; ni < 6; ni++) {
            const int col = wn2 + ni * 8 + 2 * cq;
            const float b0 = bias[col], b1 = bias[col + 1];
            size_t i00 = (((size_t)b * CC + col) * HH + h0) * WW + w0;     // (col,   h0)
            size_t i10 = i00 + (size_t)HH * WW;                            // (col+1, h0)
            size_t i01 = i00 + WW * 8 / 8 * WW;                            // placeholder
            i01 = (((size_t)b * CC + col) * HH + h0 + 1) * WW + w0;        // (col,   h0+1)  [token s0+8]
            size_t i11 = i01 + (size_t)HH * WW;                            // (col+1, h0+1)
            out[i00] = acc2[mi][ni][0] + b0 + x[i00];
            out[i10] = acc2[mi][ni][1] + b1 + x[i10];
            out[i01] = acc2[mi][ni][2] + b0 + x[i01];
            out[i11] = acc2[mi][ni][3] + b1 + x[i11];
        }
    }
}

// --------------------------------- launch ---------------------------------
extern "C" void kernel_launch(void* const* d_in, const int* in_sizes, int n_in,
                              void* d_out, int out_size) {
    const float* x     = (const float*)d_in[0];
    const float* gw    = (const float*)d_in[1];
    const float* gb    = (const float*)d_in[2];
    const float* wqkv  = (const float*)d_in[3];
    const float* wproj = (const float*)d_in[4];
    const float* bproj = (const float*)d_in[5];
    float* out = (float*)d_out;

    static cudaStream_t s2 = nullptr;
    static cudaEvent_t evFork, evCvtw, evG0, evG1, evA0, evA1;
    if (!s2) {
        cudaStreamCreateWithFlags(&s2, cudaStreamNonBlocking);
        cudaEventCreateWithFlags(&evFork, cudaEventDisableTiming);
        cudaEventCreateWithFlags(&evCvtw, cudaEventDisableTiming);
        cudaEventCreateWithFlags(&evG0,   cudaEventDisableTiming);
        cudaEventCreateWithFlags(&evG1,   cudaEventDisableTiming);
        cudaEventCreateWithFlags(&evA0,   cudaEventDisableTiming);
        cudaEventCreateWithFlags(&evA1,   cudaEventDisableTiming);
        cudaFuncSetAttribute(k_hgemm,     cudaFuncAttributeMaxDynamicSharedMemorySize, GEMM_SMEM);
        cudaFuncSetAttribute(k_attn_proj, cudaFuncAttributeMaxDynamicSharedMemorySize, ATTN_SMEM);
    }

    // fork: cvtw on s2 (independent of x-path)
    cudaEventRecord(evFork, 0);
    cudaStreamWaitEvent(s2, evFork, 0);
    k_cvtw<<<(N4Q + N4P + 255)/256, 256, 0, s2>>>(wqkv, wproj);
    cudaEventRecord(evCvtw, s2);

    k_gnstats1<<<BB * NGROUPS * 16, 256>>>(x);
    k_pack<<<dim3(3, HH, BB), 256>>>(x, gw, gb);

    // hgemm halves on default (needs cvtw)
    cudaStreamWaitEvent(0, evCvtw, 0);
    k_hgemm<<<256, 512, GEMM_SMEM>>>(3 * CC, 9, 0);
    cudaEventRecord(evG0, 0);
    k_hgemm<<<256, 512, GEMM_SMEM>>>(3 * CC, 9, 32768);
    cudaEventRecord(evG1, 0);

    // attn+proj+output halves on s2: attn0 overlaps hgemm1's tail
    cudaStreamWaitEvent(s2, evG0, 0);
    k_attn_proj<<<512, 512, ATTN_SMEM, s2>>>(bproj, x, out, 0);
    cudaEventRecord(evA0, s2);
    cudaStreamWaitEvent(s2, evG1, 0);
    k_attn_proj<<<512, 512, ATTN_SMEM, s2>>>(bproj, x, out, 512);
    cudaEventRecord(evA1, s2);

    // join forked stream back to origin before capture end
    cudaStreamWaitEvent(0, evA0, 0);
    cudaStreamWaitEvent(0, evA1, 0);
}